// round 1
// baseline (speedup 1.0000x reference)
#include <cuda_runtime.h>

// ---------------- scratch (device globals; no allocation allowed) ----------------
__device__ float g_A1[221184];    // layer1 eff weights: [(o*9+j)][kk(96)][n(16)]
__device__ float g_A2[688128];    // layer2 eff weights: [j][kk(384)][col(256)] col=o*8+n
__device__ float g_t1[4718592];   // [b][c16][j9][n8]
__device__ float g_t2[3670016];   // [b][c32][j7][l4]
__device__ float g_t3[1310720];   // [b][o*5+j]
__device__ float g_red[224];      // sum1[16] ssq1[16] sum2[32] ssq2[32] sum3[64] ssq3[64]
__device__ float g_bn1[32];       // [scale16][shift16]
__device__ float g_bn2[64];       // [scale32][shift32]
__device__ float g_bn3[128];      // [scale64][shift64]

__global__ void k_zero() {
    if (threadIdx.x < 224) g_red[threadIdx.x] = 0.f;
}

// Build layer1 effective weights. A1[(o,j),(kk=c*16+p),(n)]
// = sum_m w1[o,c,m] * hat((p-n)/h - m)/h, support clipped to |p-n| <= 3h.
__global__ void k_prep1(const float* __restrict__ w1) {
    int id = blockIdx.x * blockDim.x + threadIdx.x;
    if (id >= 221184) return;
    int n  = id & 15;
    int kk = (id >> 4) % 96;
    int oj = id / 1536;
    int o = oj / 9, j = oj % 9;
    int c = kk >> 4, p = kk & 15;
    int h = 1 << j;
    int d = p - n;
    float v = 0.f;
    if (d >= -3 * h && d <= 3 * h) {
        float t = (float)d / (float)h;
        #pragma unroll
        for (int mm = 0; mm < 7; mm++) {
            float hat = 1.f - fabsf(t - (float)(mm - 3));
            if (hat > 0.f) v += w1[(o * 6 + c) * 7 + mm] * hat;
        }
        v /= (float)h;
    }
    g_A1[id] = v;
}

// Build layer2 effective weights. A2[j][kk=(c*3+r)*8+p][col=o*8+n]
// = sum_m w2[o,c,r,m] * hat((p-n)/h - m)/h, support clipped to |p-n| <= h.
__global__ void k_prep2(const float* __restrict__ w2) {
    int id = blockIdx.x * blockDim.x + threadIdx.x;
    if (id >= 688128) return;
    int col = id & 255;
    int kk  = (id >> 8) % 384;
    int j   = id / 98304;
    int o = col >> 3, n = col & 7;
    int p = kk & 7;
    int cr = kk >> 3;               // c*3+r
    int h = 1 << j;
    int d = p - n;
    float v = 0.f;
    if (d >= -h && d <= h) {
        float t = (float)d / (float)h;
        #pragma unroll
        for (int mm = 0; mm < 3; mm++) {
            float hat = 1.f - fabsf(t - (float)(mm - 1));
            if (hat > 0.f) v += w2[(o * 48 + cr) * 3 + mm] * hat;
        }
        v /= (float)h;
    }
    g_A2[id] = v;
}

// Layer1: GEMM [32 rows x 16 n] per (o,j) block, fused pool(4,s2,p1)+relu+stats.
__global__ void __launch_bounds__(128) k_layer1(const float* __restrict__ x) {
    __shared__ float xs[32][97];
    __shared__ float ws[96][16];
    __shared__ float pre[32][17];
    __shared__ float red[128];
    int t = threadIdx.x;
    int b0 = blockIdx.x * 32;
    int oj = blockIdx.y;
    int o = oj / 9, j = oj % 9;

    for (int i = t; i < 3072; i += 128) xs[i / 96][i % 96] = x[b0 * 96 + i];
    const float* A = g_A1 + oj * 1536;
    for (int i = t; i < 1536; i += 128) ws[i >> 4][i & 15] = A[i];
    __syncthreads();

    int rb = t >> 4, n = t & 15;
    float a0 = 0, a1 = 0, a2 = 0, a3 = 0;
    #pragma unroll 4
    for (int kk = 0; kk < 96; kk++) {
        float wv = ws[kk][n];
        a0 += xs[rb][kk] * wv;
        a1 += xs[rb + 8][kk] * wv;
        a2 += xs[rb + 16][kk] * wv;
        a3 += xs[rb + 24][kk] * wv;
    }
    pre[rb][n] = a0; pre[rb + 8][n] = a1; pre[rb + 16][n] = a2; pre[rb + 24][n] = a3;
    __syncthreads();

    float s = 0, ss = 0;
    #pragma unroll
    for (int q = 0; q < 2; q++) {
        int idx = t + q * 128;
        int r = idx >> 3, k = idx & 7;
        int lo = 2 * k - 1; if (lo < 0) lo = 0;
        int hi = 2 * k + 2; if (hi > 15) hi = 15;
        float m = -1e30f;
        for (int nn = lo; nn <= hi; nn++) m = fmaxf(m, pre[r][nn]);
        m = fmaxf(m, 0.f);
        g_t1[(b0 + r) * 1152 + o * 72 + j * 8 + k] = m;
        s += m; ss += m * m;
    }
    red[t] = s; __syncthreads();
    for (int w = 64; w > 0; w >>= 1) { if (t < w) red[t] += red[t + w]; __syncthreads(); }
    if (t == 0) atomicAdd(&g_red[o], red[0]);
    __syncthreads();
    red[t] = ss; __syncthreads();
    for (int w = 64; w > 0; w >>= 1) { if (t < w) red[t] += red[t + w]; __syncthreads(); }
    if (t == 0) atomicAdd(&g_red[16 + o], red[0]);
}

__global__ void k_bnparam(const float* __restrict__ g, const float* __restrict__ b, int layer) {
    int c = threadIdx.x;
    int nch, off; float count; float* bn;
    if (layer == 1)      { nch = 16; off = 0;  count = 294912.f; bn = g_bn1; }
    else if (layer == 2) { nch = 32; off = 32; count = 114688.f; bn = g_bn2; }
    else                 { nch = 64; off = 96; count = 20480.f;  bn = g_bn3; }
    if (c >= nch) return;
    float sum = g_red[off + c], ssq = g_red[off + nch + c];
    float mean = sum / count;
    float var = ssq / count - mean * mean;
    float sc = g[c] * rsqrtf(var + 2e-5f);
    bn[c] = sc;
    bn[nch + c] = b[c] - mean * sc;
}

// Layer2: per (batch-tile of 32, j): GEMM [32 x 256] with K=384 (BN1 folded into
// smem load), fused register pooling + relu + stats. Thread = 4 rows x one o2.
__global__ void __launch_bounds__(256) k_layer2() {
    extern __shared__ float sm[];          // acts [32][stride 388]
    int t = threadIdx.x;
    int b0 = blockIdx.x * 32;
    int j = blockIdx.y;
    float* acts = sm;
    for (int i = t; i < 12288; i += 256) {
        int r = i / 384, k = i % 384;
        int c = k / 24, rem = k % 24;
        int rr = rem >> 3, p = rem & 7;
        float v = g_t1[(b0 + r) * 1152 + c * 72 + (j + rr) * 8 + p];
        acts[r * 388 + k] = v * g_bn1[c] + g_bn1[16 + c];
    }
    __syncthreads();

    int rg = t & 7, cg = t >> 3;           // cg == o2
    const float* Wp = g_A2 + j * 98304 + cg * 8;
    float acc[4][8];
    #pragma unroll
    for (int q = 0; q < 4; q++)
        #pragma unroll
        for (int i = 0; i < 8; i++) acc[q][i] = 0.f;
    const float* ar0 = acts + rg * 388;
    const float* ar1 = acts + (rg + 8) * 388;
    const float* ar2 = acts + (rg + 16) * 388;
    const float* ar3 = acts + (rg + 24) * 388;
    #pragma unroll 2
    for (int kk = 0; kk < 384; kk++) {
        float4 wa = *reinterpret_cast<const float4*>(Wp);
        float4 wb = *reinterpret_cast<const float4*>(Wp + 4);
        Wp += 256;
        float wv[8] = {wa.x, wa.y, wa.z, wa.w, wb.x, wb.y, wb.z, wb.w};
        float av[4] = {ar0[kk], ar1[kk], ar2[kk], ar3[kk]};
        #pragma unroll
        for (int q = 0; q < 4; q++)
            #pragma unroll
            for (int i = 0; i < 8; i++) acc[q][i] += av[q] * wv[i];
    }

    float s = 0, ss = 0;
    #pragma unroll
    for (int q = 0; q < 4; q++) {
        int row = rg + 8 * q;
        #pragma unroll
        for (int k = 0; k < 4; k++) {
            int lo = 2 * k - 1; if (lo < 0) lo = 0;
            int hi = 2 * k + 2; if (hi > 7) hi = 7;
            float m = -1e30f;
            for (int nn = lo; nn <= hi; nn++) m = fmaxf(m, acc[q][nn]);
            m = fmaxf(m, 0.f);
            g_t2[(b0 + row) * 896 + cg * 28 + j * 4 + k] = m;
            s += m; ss += m * m;
        }
    }
    __syncthreads();
    if (t < 64) sm[t] = 0.f;
    __syncthreads();
    atomicAdd(&sm[cg], s);
    atomicAdd(&sm[32 + cg], ss);
    __syncthreads();
    if (t < 32) { atomicAdd(&g_red[32 + t], sm[t]); atomicAdd(&g_red[64 + t], sm[32 + t]); }
}

// Layer3: per batch-tile of 16: full t2 slice in smem (BN2 folded on load),
// contraction over (c=32, k=3) for 3 surviving l positions, pool+relu+stats.
__global__ void __launch_bounds__(256) k_layer3(const float* __restrict__ w3) {
    extern __shared__ float sm[];          // acts 14336 | ws 6144
    __shared__ float st[128];
    float* acts = sm;
    float* ws = sm + 14336;
    int t = threadIdx.x;
    int b0 = blockIdx.x * 16;
    for (int i = t; i < 14336; i += 256) {
        int k = i % 896;
        int c = k / 28;
        acts[i] = g_t2[b0 * 896 + i] * g_bn2[c] + g_bn2[32 + c];
    }
    for (int i = t; i < 6144; i += 256) ws[i] = w3[i];  // w3[...,0]: last dim is 1
    __syncthreads();

    int o3 = t & 63, rb = t >> 6;
    const float* wo = ws + o3 * 96;
    const float invj[5] = {1.f, 0.5f, 0.25f, 0.125f, 0.0625f};
    float s = 0, ssq = 0;
    for (int q = 0; q < 4; q++) {
        int row = rb * 4 + q;
        const float* arow = acts + row * 896;
        float accs[15];
        #pragma unroll
        for (int i = 0; i < 15; i++) accs[i] = 0.f;
        for (int c = 0; c < 32; c++) {
            float a[28];
            #pragma unroll
            for (int i = 0; i < 28; i++) a[i] = arow[c * 28 + i];
            float w0 = wo[c * 3], w1v = wo[c * 3 + 1], w2v = wo[c * 3 + 2];
            #pragma unroll
            for (int jj = 0; jj < 5; jj++)
                #pragma unroll
                for (int l = 0; l < 3; l++)
                    accs[jj * 3 + l] += w0 * a[jj * 4 + l]
                                      + w1v * a[(jj + 1) * 4 + l]
                                      + w2v * a[(jj + 2) * 4 + l];
        }
        #pragma unroll
        for (int jj = 0; jj < 5; jj++) {
            float m = fmaxf(fmaxf(accs[jj * 3], accs[jj * 3 + 1]), accs[jj * 3 + 2]);
            m = fmaxf(m * invj[jj], 0.f);
            g_t3[(b0 + row) * 320 + o3 * 5 + jj] = m;
            s += m; ssq += m * m;
        }
    }
    if (t < 128) st[t] = 0.f;
    __syncthreads();
    atomicAdd(&st[o3], s);
    atomicAdd(&st[64 + o3], ssq);
    __syncthreads();
    if (t < 64) { atomicAdd(&g_red[96 + t], st[t]); atomicAdd(&g_red[160 + t], st[64 + t]); }
}

// BN3 + 3-layer MLP. One thread per sample; t3 tiles staged through smem.
__global__ void __launch_bounds__(128) k_fc(const float* __restrict__ fw1, const float* __restrict__ fb1,
                                            const float* __restrict__ fw2, const float* __restrict__ fb2,
                                            const float* __restrict__ fw3, const float* __restrict__ fb3,
                                            float* __restrict__ out) {
    __shared__ float w1s[5120];            // transposed [k][o]
    __shared__ float vt[128 * 33];
    __shared__ float w2s[256];
    __shared__ float w3s[272];
    __shared__ float b1s[16], b2s[16], b3s[17];
    int t = threadIdx.x;
    int bbase = blockIdx.x * 128;
    for (int i = t; i < 5120; i += 128) { int o = i / 320, k = i % 320; w1s[k * 16 + o] = fw1[i]; }
    for (int i = t; i < 256; i += 128) w2s[i] = fw2[i];
    for (int i = t; i < 272; i += 128) w3s[i] = fw3[i];
    if (t < 16) { b1s[t] = fb1[t]; b2s[t] = fb2[t]; }
    if (t < 17) b3s[t] = fb3[t];
    __syncthreads();

    float h1[16];
    #pragma unroll
    for (int o = 0; o < 16; o++) h1[o] = b1s[o];

    for (int i0 = 0; i0 < 320; i0 += 32) {
        __syncthreads();
        for (int idx = t; idx < 4096; idx += 128) {
            int r = idx >> 5, c2 = idx & 31;
            int i = i0 + c2, ch = i / 5;
            vt[r * 33 + c2] = g_t3[(bbase + r) * 320 + i] * g_bn3[ch] + g_bn3[64 + ch];
        }
        __syncthreads();
        #pragma unroll 4
        for (int c2 = 0; c2 < 32; c2++) {
            float v = vt[t * 33 + c2];
            const float* wr = &w1s[(i0 + c2) * 16];
            #pragma unroll
            for (int o = 0; o < 16; o++) h1[o] += v * wr[o];
        }
    }
    float h2[16];
    #pragma unroll
    for (int o = 0; o < 16; o++) {
        float a = b2s[o];
        #pragma unroll
        for (int k = 0; k < 16; k++) a += h1[k] * w2s[o * 16 + k];
        h2[o] = a;
    }
    int b = bbase + t;
    #pragma unroll
    for (int o = 0; o < 17; o++) {
        float a = b3s[o];
        #pragma unroll
        for (int k = 0; k < 16; k++) a += h2[k] * w3s[o * 16 + k];
        out[b * 17 + o] = a;
    }
}

extern "C" void kernel_launch(void* const* d_in, const int* in_sizes, int n_in,
                              void* d_out, int out_size) {
    const float* x   = (const float*)d_in[0];
    const float* w1  = (const float*)d_in[1];
    const float* w2  = (const float*)d_in[2];
    const float* w3  = (const float*)d_in[3];
    const float* g1  = (const float*)d_in[4];
    const float* b1  = (const float*)d_in[5];
    const float* g2  = (const float*)d_in[6];
    const float* b2  = (const float*)d_in[7];
    const float* g3  = (const float*)d_in[8];
    const float* b3  = (const float*)d_in[9];
    const float* fw1 = (const float*)d_in[10];
    const float* fb1 = (const float*)d_in[11];
    const float* fw2 = (const float*)d_in[12];
    const float* fb2 = (const float*)d_in[13];
    const float* fw3 = (const float*)d_in[14];
    const float* fb3 = (const float*)d_in[15];
    float* out = (float*)d_out;

    cudaFuncSetAttribute(k_layer2, cudaFuncAttributeMaxDynamicSharedMemorySize, 49664);
    cudaFuncSetAttribute(k_layer3, cudaFuncAttributeMaxDynamicSharedMemorySize, 81920);

    k_zero<<<1, 256>>>();
    k_prep1<<<(221184 + 255) / 256, 256>>>(w1);
    k_prep2<<<(688128 + 255) / 256, 256>>>(w2);
    k_layer1<<<dim3(128, 144), 128>>>(x);
    k_bnparam<<<1, 64>>>(g1, b1, 1);
    k_layer2<<<dim3(128, 7), 256, 49664>>>();
    k_bnparam<<<1, 64>>>(g2, b2, 2);
    k_layer3<<<256, 256, 81920>>>(w3);
    k_bnparam<<<1, 64>>>(g3, b3, 3);
    k_fc<<<32, 128>>>(fw1, fb1, fw2, fb2, fw3, fb3, out);
}